// round 8
// baseline (speedup 1.0000x reference)
#include <cuda_runtime.h>
#include <math.h>

// Problem constants
#define B 256
#define T 96
#define F 368
#define H 368
#define G3 1104          // 3*H
#define NC 29
#define OUT_NMS_OFF   (B*T)
#define OUT_FINE_OFF  (B*T + B*T*2)

// gru persistent config
#define NCB 62
#define GRID_REC 124
#define THR_REC 512

// ---------------- device scratch ----------------
__device__ float g_xprojT[(size_t)T * G3 * B];      // (t, g, b)  b contiguous
__device__ float g_temporalT[(size_t)T * H * B];    // (t, k, b)  b contiguous
__device__ float g_logits[(size_t)B * T * 32];      // (t, b, 32) logits
__device__ float g_scores[(size_t)B * T * 2];
__device__ unsigned g_arrive[2][NCB * 32];
__device__ unsigned g_release[64];

// ---------------- f32x2 packed helpers ----------------
__device__ __forceinline__ unsigned long long fma2(unsigned long long a,
                                                   unsigned long long b,
                                                   unsigned long long c) {
    unsigned long long d;
    asm("fma.rn.f32x2 %0, %1, %2, %3;" : "=l"(d) : "l"(a), "l"(b), "l"(c));
    return d;
}
__device__ __forceinline__ unsigned long long add2(unsigned long long a,
                                                   unsigned long long b) {
    unsigned long long d;
    asm("add.rn.f32x2 %0, %1, %2;" : "=l"(d) : "l"(a), "l"(b));
    return d;
}
__device__ __forceinline__ unsigned long long packdup(float x) {
    unsigned long long r;
    unsigned u = __float_as_uint(x);
    asm("mov.b64 %0, {%1, %1};" : "=l"(r) : "r"(u));
    return r;
}
__device__ __forceinline__ float lo32(unsigned long long v) {
    return __uint_as_float((unsigned)v);
}
__device__ __forceinline__ float hi32(unsigned long long v) {
    return __uint_as_float((unsigned)(v >> 32));
}
__device__ __forceinline__ float fsigmoid(float x) {
    return 1.f / (1.f + __expf(-x));
}
__device__ __forceinline__ float ftanh(float x) {
    float ex = __expf(2.f * x);
    return 1.f - 2.f / (ex + 1.f);
}

// ---------------- Kernel 1: xproj = feat @ Wi^T + bi ----------------
#define BK 16
__global__ __launch_bounds__(256) void xproj_gemm(const float* __restrict__ feat,
                                                  const float* __restrict__ Wi,
                                                  const float* __restrict__ bi) {
    __shared__ float As[BK][128];
    __shared__ float Ws[BK][64];
    __shared__ float sC[128 * 65];
    const int t  = blockIdx.x >> 1;
    const int b0 = (blockIdx.x & 1) * 128;
    const int bn = blockIdx.y * 64;
    const int tid = threadIdx.x;
    const int tx = tid % 16;
    const int ty = tid / 16;

    unsigned long long acc2[4][4];
#pragma unroll
    for (int i = 0; i < 4; i++)
#pragma unroll
        for (int j = 0; j < 4; j++) acc2[i][j] = 0ull;

    for (int kt = 0; kt < F; kt += BK) {
#pragma unroll
        for (int l = 0; l < 2; l++) {
            int idx = tid + l * 256;
            int row = idx >> 2;
            int kq = idx & 3;
            float4 v = *(const float4*)(feat + ((size_t)(b0 + row) * T + t) * F + kt + kq * 4);
            As[kq * 4 + 0][row] = v.x;
            As[kq * 4 + 1][row] = v.y;
            As[kq * 4 + 2][row] = v.z;
            As[kq * 4 + 3][row] = v.w;
        }
        {
            int m = tid >> 2;
            int kq = tid & 3;
            int g = bn + m;
            float4 v = make_float4(0.f, 0.f, 0.f, 0.f);
            if (g < G3) v = *(const float4*)(Wi + (size_t)g * F + kt + kq * 4);
            Ws[kq * 4 + 0][m] = v.x;
            Ws[kq * 4 + 1][m] = v.y;
            Ws[kq * 4 + 2][m] = v.z;
            Ws[kq * 4 + 3][m] = v.w;
        }
        __syncthreads();
#pragma unroll
        for (int k = 0; k < BK; k++) {
            unsigned long long a2[4];
#pragma unroll
            for (int i = 0; i < 4; i++)
                a2[i] = *(const unsigned long long*)&As[k][ty * 8 + 2 * i];
            float4 wv = *(const float4*)&Ws[k][tx * 4];
            unsigned long long wd[4];
            wd[0] = packdup(wv.x); wd[1] = packdup(wv.y);
            wd[2] = packdup(wv.z); wd[3] = packdup(wv.w);
#pragma unroll
            for (int i = 0; i < 4; i++)
#pragma unroll
                for (int j = 0; j < 4; j++)
                    acc2[i][j] = fma2(a2[i], wd[j], acc2[i][j]);
        }
        __syncthreads();
    }

#pragma unroll
    for (int i = 0; i < 4; i++) {
        int r0 = ty * 8 + 2 * i;
#pragma unroll
        for (int j = 0; j < 4; j++) {
            int g = tx * 4 + j;
            sC[(size_t)r0 * 65 + g]       = lo32(acc2[i][j]);
            sC[(size_t)(r0 + 1) * 65 + g] = hi32(acc2[i][j]);
        }
    }
    __syncthreads();
    for (int q = tid; q < 64 * 128; q += 256) {
        int g = q >> 7;
        int b = q & 127;
        int gg = bn + g;
        if (gg < G3) {
            float v = sC[(size_t)b * 65 + g] + __ldg(bi + gg);
            g_xprojT[((size_t)t * G3 + gg) * B + b0 + b] = v;
        }
    }
}

// ---------------- barrier reset (split in two so gru lands in profiled slot) ----------------
__global__ void reset_arrive_kernel() {
    int tid = threadIdx.x;
    for (int q = tid; q < 2 * NCB * 32; q += 256) {
        ((unsigned*)g_arrive)[q] = 0u;
    }
}
__global__ void reset_release_kernel() {
    if (threadIdx.x < 64) g_release[threadIdx.x] = 0u;
}

// ---------------- per-half grid barrier ----------------
__device__ __forceinline__ void half_barrier(int bh, int cb, unsigned s) {
    __syncthreads();
    if (threadIdx.x == 0) {
        __threadfence();
        *(volatile unsigned*)&g_arrive[bh][cb * 32] = s;
    }
    if (cb == 0 && threadIdx.x < 31) {
        int i0 = threadIdx.x * 2;
        int i1 = i0 + 1;
        bool done = false;
        while (!done) {
            unsigned a = *(volatile unsigned*)&g_arrive[bh][i0 * 32];
            unsigned c = (i1 < NCB) ? *(volatile unsigned*)&g_arrive[bh][i1 * 32] : s;
            done = __all_sync(0x7fffffffu, (a >= s) && (c >= s));
        }
        if (threadIdx.x == 0) {
            __threadfence();
            *(volatile unsigned*)&g_release[bh * 32] = s;
        }
    }
    if (threadIdx.x == 0) {
        while (*(volatile unsigned*)&g_release[bh * 32] < s) { }
        __threadfence();
    }
    __syncthreads();
}

// ---------------- persistent GRU recurrence ----------------
__global__ __launch_bounds__(THR_REC) void gru_persistent(const float* __restrict__ Wh,
                                                          const float* __restrict__ bhb) {
    __shared__ float wsp[9 * H * 2];
    __shared__ unsigned long long red[THR_REC * 9];
    const int tid = threadIdx.x;
    const int bh = blockIdx.x & 1;
    const int cb = blockIdx.x >> 1;
    const int j0 = cb * 6;
    const int cg = tid >> 7;
    const int b  = bh * 128 + (tid & 127);
    const int k0 = cg * 92;

    const int gp  = tid >> 7;
    const int gb2 = tid & 127;
    const int gbb = bh * 128 + gb2;
    const int gja = j0 + 2 * gp;
    const bool gate = (tid < 384) && (gja < H);

    for (int q = tid; q < 9 * H; q += THR_REC) {
        int row = q / H;
        int k   = q % H;
        int p = row / 3, g = row % 3;
        int ja = j0 + 2 * p, jb = ja + 1;
        float lo = (ja < H) ? Wh[((size_t)g * H + ja) * H + k] : 0.f;
        float hi = (jb < H) ? Wh[((size_t)g * H + jb) * H + k] : 0.f;
        wsp[(size_t)q * 2 + 0] = lo;
        wsp[(size_t)q * 2 + 1] = hi;
    }
    float gbias[2][3];
    if (gate) {
#pragma unroll
        for (int c = 0; c < 2; c++)
#pragma unroll
            for (int g = 0; g < 3; g++)
                gbias[c][g] = bhb[g * H + gja + c];
    }
    // hoisted per-row SMEM base pointers (k0 folded in)
    const float* wbase[9];
#pragma unroll
    for (int r = 0; r < 9; r++) wbase[r] = wsp + ((size_t)r * H + k0) * 2;
    __syncthreads();

    for (int t = 0; t < T; t++) {
        const float* hprevT = g_temporalT + (size_t)(t - 1) * H * B;

        float gi[2][3];
        float hp[2];
        if (gate) {
            const float* xp = g_xprojT + (size_t)t * G3 * B;
#pragma unroll
            for (int c = 0; c < 2; c++) {
                int j = gja + c;
                gi[c][0] = xp[((size_t)(0 * H + j)) * B + gbb];
                gi[c][1] = xp[((size_t)(1 * H + j)) * B + gbb];
                gi[c][2] = xp[((size_t)(2 * H + j)) * B + gbb];
                hp[c] = (t > 0) ? hprevT[(size_t)j * B + gbb] : 0.f;
            }
        }

        unsigned long long acc[9];
#pragma unroll
        for (int r = 0; r < 9; r++) acc[r] = 0ull;

        if (t > 0) {
            const float* hk = hprevT + (size_t)k0 * B + b;
#pragma unroll 2
            for (int k4 = 0; k4 < 23; k4++) {
                float h0 = hk[0 * B];
                float h1 = hk[1 * B];
                float h2 = hk[2 * B];
                float h3 = hk[3 * B];
                hk += 4 * B;
                unsigned long long hd0 = packdup(h0), hd1 = packdup(h1);
                unsigned long long hd2 = packdup(h2), hd3 = packdup(h3);
#pragma unroll
                for (int r = 0; r < 9; r++) {
                    const float* wp = wbase[r] + k4 * 8;
                    ulonglong2 wA = *(const ulonglong2*)(wp);
                    ulonglong2 wB = *(const ulonglong2*)(wp + 4);
                    acc[r] = fma2(hd0, wA.x, acc[r]);
                    acc[r] = fma2(hd1, wA.y, acc[r]);
                    acc[r] = fma2(hd2, wB.x, acc[r]);
                    acc[r] = fma2(hd3, wB.y, acc[r]);
                }
            }
        }

        {
            unsigned long long* dst = red + (size_t)tid * 9;
#pragma unroll
            for (int r = 0; r < 9; r++) dst[r] = acc[r];
        }
        __syncthreads();

        if (gate) {
            unsigned long long s[3];
#pragma unroll
            for (int g = 0; g < 3; g++) {
                int r = gp * 3 + g;
                unsigned long long v = red[((size_t)0 * 128 + gb2) * 9 + r];
                v = add2(v, red[((size_t)1 * 128 + gb2) * 9 + r]);
                v = add2(v, red[((size_t)2 * 128 + gb2) * 9 + r]);
                v = add2(v, red[((size_t)3 * 128 + gb2) * 9 + r]);
                s[g] = v;
            }
            float* houtT = g_temporalT + (size_t)t * H * B;
#pragma unroll
            for (int c = 0; c < 2; c++) {
                int j = gja + c;
                float gh_r = ((c == 0) ? lo32(s[0]) : hi32(s[0])) + gbias[c][0];
                float gh_z = ((c == 0) ? lo32(s[1]) : hi32(s[1])) + gbias[c][1];
                float gh_n = ((c == 0) ? lo32(s[2]) : hi32(s[2])) + gbias[c][2];
                float r = fsigmoid(gi[c][0] + gh_r);
                float z = fsigmoid(gi[c][1] + gh_z);
                float n = ftanh(gi[c][2] + r * gh_n);
                houtT[(size_t)j * B + gbb] = (1.f - z) * n + z * hp[c];
            }
        }

        if (t < T - 1) half_barrier(bh, cb, (unsigned)(t + 1));
    }
}

// ---------------- Kernel 3a: heads GEMM -> logits ----------------
// block = (t, b-half 128) x 32 n.  A from g_temporalT (k rows, b contiguous).
__global__ __launch_bounds__(256) void heads_gemm(const float* __restrict__ Wc,
                                                  const float* __restrict__ bc,
                                                  const float* __restrict__ Wf,
                                                  const float* __restrict__ bf) {
    __shared__ float As[BK][128];
    __shared__ float Ws[BK][32];
    const int t  = blockIdx.x >> 1;
    const int b0 = (blockIdx.x & 1) * 128;
    const int tid = threadIdx.x;
    const int tx = tid % 8;     // n dir: 8*4 = 32
    const int ty = tid / 8;     // b dir: 32*4 = 128

    float acc[4][4];
#pragma unroll
    for (int i = 0; i < 4; i++)
#pragma unroll
        for (int j = 0; j < 4; j++) acc[i][j] = 0.f;

    const float* hT = g_temporalT + (size_t)t * H * B;

    for (int kt = 0; kt < H; kt += BK) {
        // As: 16 k-rows x 128 b = 512 float4, 2 per thread; coalesced rows
#pragma unroll
        for (int l = 0; l < 2; l++) {
            int idx = tid + l * 256;
            int krow = idx >> 5;
            int bq = idx & 31;
            *(float4*)&As[krow][bq * 4] =
                *(const float4*)(hT + (size_t)(kt + krow) * B + b0 + bq * 4);
        }
        // Ws: 32 n x 16 k, 128 float4 by threads < 128
        if (tid < 128) {
            int n = tid >> 2;
            int kq = tid & 3;
            float4 v = make_float4(0.f, 0.f, 0.f, 0.f);
            if (n < 2)       v = *(const float4*)(Wc + (size_t)n * H + kt + kq * 4);
            else if (n < 31) v = *(const float4*)(Wf + (size_t)(n - 2) * H + kt + kq * 4);
            Ws[kq * 4 + 0][n] = v.x;
            Ws[kq * 4 + 1][n] = v.y;
            Ws[kq * 4 + 2][n] = v.z;
            Ws[kq * 4 + 3][n] = v.w;
        }
        __syncthreads();
#pragma unroll
        for (int k = 0; k < BK; k++) {
            float a[4], w[4];
            *(float4*)a = *(const float4*)&As[k][ty * 4];
            *(float4*)w = *(const float4*)&Ws[k][tx * 4];
#pragma unroll
            for (int i = 0; i < 4; i++)
#pragma unroll
                for (int j = 0; j < 4; j++)
                    acc[i][j] = fmaf(a[i], w[j], acc[i][j]);
        }
        __syncthreads();
    }

    // epilogue: + bias, write (t, b, n) logits
#pragma unroll
    for (int i = 0; i < 4; i++) {
        int b = b0 + ty * 4 + i;
        float4 v;
        float* vp = (float*)&v;
#pragma unroll
        for (int j = 0; j < 4; j++) {
            int n = tx * 4 + j;
            float bias = (n < 2) ? bc[n] : ((n < 31) ? bf[n - 2] : 0.f);
            vp[j] = acc[i][j] + bias;
        }
        *(float4*)&g_logits[((size_t)t * B + b) * 32 + tx * 4] = v;
    }
}

// ---------------- Kernel 3b: activations ----------------
__global__ __launch_bounds__(256) void act_kernel(float* __restrict__ out) {
    int idx = blockIdx.x * blockDim.x + threadIdx.x;
    if (idx >= B * T) return;
    int t = idx >> 8;
    int b = idx & 255;
    const float* lg = g_logits + (size_t)idx * 32;
    float logit[32];
#pragma unroll
    for (int q = 0; q < 8; q++)
        *(float4*)&logit[q * 4] = *(const float4*)&lg[q * 4];

    float l0 = logit[0], l1 = logit[1];
    float m = fmaxf(l0, l1);
    float e0 = __expf(l0 - m), e1 = __expf(l1 - m);
    float inv = 1.f / (e0 + e1);
    size_t oidx = (size_t)b * T + t;
    g_scores[oidx * 2 + 0] = e0 * inv;
    g_scores[oidx * 2 + 1] = e1 * inv;

    float* fine = out + OUT_FINE_OFF + oidx * NC;
#pragma unroll
    for (int i = 0; i < NC; i++) fine[i] = fsigmoid(logit[2 + i]);
}

// ---------------- Kernel 4: NMS + decisions ----------------
__global__ void nms_kernel(float* __restrict__ out) {
    int idx = blockIdx.x * blockDim.x + threadIdx.x;
    if (idx >= B * T) return;
    int b = idx / T;
    int t = idx % T;
    const float* sb = g_scores + (size_t)b * T * 2;
    float s0 = sb[t * 2 + 0];
    float s1 = sb[t * 2 + 1];
    float wmin = INFINITY;
#pragma unroll
    for (int k = -2; k <= 2; k++) {
        int tt = t + k;
        if (tt >= 0 && tt < T) wmin = fminf(wmin, sb[tt * 2]);
    }
    bool keep = (s0 == wmin);
    float o0 = keep ? s0 : 0.f;
    float o1 = keep ? s1 : 0.f;
    out[idx] = (o1 > o0) ? 1.0f : 0.0f;
    out[OUT_NMS_OFF + (size_t)idx * 2 + 0] = o0;
    out[OUT_NMS_OFF + (size_t)idx * 2 + 1] = o1;
}

// ---------------- launch ----------------
extern "C" void kernel_launch(void* const* d_in, const int* in_sizes, int n_in,
                              void* d_out, int out_size) {
    const float* feat = (const float*)d_in[0];
    const float* Wi  = (const float*)d_in[2];
    const float* Wh  = (const float*)d_in[3];
    const float* bi  = (const float*)d_in[4];
    const float* bhb = (const float*)d_in[5];
    const float* Wc  = (const float*)d_in[6];
    const float* bc  = (const float*)d_in[7];
    const float* Wf  = (const float*)d_in[8];
    const float* bf  = (const float*)d_in[9];
    float* out = (float*)d_out;

    // launch order arranged so the ncu-profiled slot (4th launch) hits gru_persistent
    reset_arrive_kernel<<<1, 256>>>();                 // 1
    dim3 g1(T * 2, (G3 + 63) / 64);
    xproj_gemm<<<g1, 256>>>(feat, Wi, bi);             // 2
    reset_release_kernel<<<1, 64>>>();                 // 3
    gru_persistent<<<GRID_REC, THR_REC>>>(Wh, bhb);    // 4  <- profiled
    heads_gemm<<<T * 2, 256>>>(Wc, bc, Wf, bf);        // 5
    act_kernel<<<(B * T + 255) / 256, 256>>>(out);     // 6
    nms_kernel<<<(B * T + 255) / 256, 256>>>(out);     // 7
}

// round 9
// speedup vs baseline: 1.1695x; 1.1695x over previous
#include <cuda_runtime.h>
#include <math.h>

// Problem constants
#define B 256
#define T 96
#define F 368
#define H 368
#define G3 1104          // 3*H
#define NC 29
#define OUT_NMS_OFF   (B*T)
#define OUT_FINE_OFF  (B*T + B*T*2)

// gru persistent config
#define NCB 62
#define GRID_REC 124
#define THR_REC 512

// ---------------- device scratch ----------------
__device__ float g_xprojT[(size_t)T * G3 * B];      // (t, g, b)  b contiguous
__device__ float g_temporalT[(size_t)T * H * B];    // (t, k, b)  b contiguous
__device__ float g_logits[(size_t)B * T * 32];
__device__ float g_scores[(size_t)B * T * 2];
__device__ unsigned g_arrive[2][NCB * 32];
__device__ unsigned g_release[64];

// ---------------- f32x2 packed helpers ----------------
__device__ __forceinline__ unsigned long long fma2(unsigned long long a,
                                                   unsigned long long b,
                                                   unsigned long long c) {
    unsigned long long d;
    asm("fma.rn.f32x2 %0, %1, %2, %3;" : "=l"(d) : "l"(a), "l"(b), "l"(c));
    return d;
}
__device__ __forceinline__ unsigned long long add2(unsigned long long a,
                                                   unsigned long long b) {
    unsigned long long d;
    asm("add.rn.f32x2 %0, %1, %2;" : "=l"(d) : "l"(a), "l"(b));
    return d;
}
__device__ __forceinline__ unsigned long long packdup(float x) {
    unsigned long long r;
    unsigned u = __float_as_uint(x);
    asm("mov.b64 %0, {%1, %1};" : "=l"(r) : "r"(u));
    return r;
}
__device__ __forceinline__ float lo32(unsigned long long v) {
    return __uint_as_float((unsigned)v);
}
__device__ __forceinline__ float hi32(unsigned long long v) {
    return __uint_as_float((unsigned)(v >> 32));
}
__device__ __forceinline__ float fsigmoid(float x) {
    return 1.f / (1.f + __expf(-x));
}
__device__ __forceinline__ float ftanh(float x) {
    float ex = __expf(2.f * x);
    return 1.f - 2.f / (ex + 1.f);
}

// ---------------- Kernel 1: xproj = feat @ Wi^T + bi ----------------
#define BK 16
__global__ __launch_bounds__(256) void xproj_gemm(const float* __restrict__ feat,
                                                  const float* __restrict__ Wi,
                                                  const float* __restrict__ bi) {
    __shared__ float As[BK][128];
    __shared__ float Ws[BK][64];
    __shared__ float sC[128 * 65];
    const int t  = blockIdx.x >> 1;
    const int b0 = (blockIdx.x & 1) * 128;
    const int bn = blockIdx.y * 64;
    const int tid = threadIdx.x;
    const int tx = tid % 16;
    const int ty = tid / 16;

    unsigned long long acc2[4][4];
#pragma unroll
    for (int i = 0; i < 4; i++)
#pragma unroll
        for (int j = 0; j < 4; j++) acc2[i][j] = 0ull;

    for (int kt = 0; kt < F; kt += BK) {
#pragma unroll
        for (int l = 0; l < 2; l++) {
            int idx = tid + l * 256;
            int row = idx >> 2;
            int kq = idx & 3;
            float4 v = *(const float4*)(feat + ((size_t)(b0 + row) * T + t) * F + kt + kq * 4);
            As[kq * 4 + 0][row] = v.x;
            As[kq * 4 + 1][row] = v.y;
            As[kq * 4 + 2][row] = v.z;
            As[kq * 4 + 3][row] = v.w;
        }
        {
            int m = tid >> 2;
            int kq = tid & 3;
            int g = bn + m;
            float4 v = make_float4(0.f, 0.f, 0.f, 0.f);
            if (g < G3) v = *(const float4*)(Wi + (size_t)g * F + kt + kq * 4);
            Ws[kq * 4 + 0][m] = v.x;
            Ws[kq * 4 + 1][m] = v.y;
            Ws[kq * 4 + 2][m] = v.z;
            Ws[kq * 4 + 3][m] = v.w;
        }
        __syncthreads();
#pragma unroll
        for (int k = 0; k < BK; k++) {
            unsigned long long a2[4];
#pragma unroll
            for (int i = 0; i < 4; i++)
                a2[i] = *(const unsigned long long*)&As[k][ty * 8 + 2 * i];
            float4 wv = *(const float4*)&Ws[k][tx * 4];
            unsigned long long wd[4];
            wd[0] = packdup(wv.x); wd[1] = packdup(wv.y);
            wd[2] = packdup(wv.z); wd[3] = packdup(wv.w);
#pragma unroll
            for (int i = 0; i < 4; i++)
#pragma unroll
                for (int j = 0; j < 4; j++)
                    acc2[i][j] = fma2(a2[i], wd[j], acc2[i][j]);
        }
        __syncthreads();
    }

#pragma unroll
    for (int i = 0; i < 4; i++) {
        int r0 = ty * 8 + 2 * i;
#pragma unroll
        for (int j = 0; j < 4; j++) {
            int g = tx * 4 + j;
            sC[(size_t)r0 * 65 + g]       = lo32(acc2[i][j]);
            sC[(size_t)(r0 + 1) * 65 + g] = hi32(acc2[i][j]);
        }
    }
    __syncthreads();
    for (int q = tid; q < 64 * 128; q += 256) {
        int g = q >> 7;
        int b = q & 127;
        int gg = bn + g;
        if (gg < G3) {
            float v = sC[(size_t)b * 65 + g] + __ldg(bi + gg);
            g_xprojT[((size_t)t * G3 + gg) * B + b0 + b] = v;
        }
    }
}

// ---------------- barrier resets ----------------
__global__ void reset_arrive_kernel() {
    int tid = threadIdx.x;
    for (int q = tid; q < 2 * NCB * 32; q += 256) {
        ((unsigned*)g_arrive)[q] = 0u;
    }
}
__global__ void reset_release_kernel() {
    if (threadIdx.x < 64) g_release[threadIdx.x] = 0u;
}

// ---------------- per-half grid barrier ----------------
__device__ __forceinline__ void half_barrier(int bh, int cb, unsigned s) {
    __syncthreads();
    if (threadIdx.x == 0) {
        __threadfence();
        *(volatile unsigned*)&g_arrive[bh][cb * 32] = s;
    }
    if (cb == 0 && threadIdx.x < 31) {
        int i0 = threadIdx.x * 2;
        int i1 = i0 + 1;
        bool done = false;
        while (!done) {
            unsigned a = *(volatile unsigned*)&g_arrive[bh][i0 * 32];
            unsigned c = (i1 < NCB) ? *(volatile unsigned*)&g_arrive[bh][i1 * 32] : s;
            done = __all_sync(0x7fffffffu, (a >= s) && (c >= s));
        }
        if (threadIdx.x == 0) {
            __threadfence();
            *(volatile unsigned*)&g_release[bh * 32] = s;
        }
    }
    if (threadIdx.x == 0) {
        while (*(volatile unsigned*)&g_release[bh * 32] < s) { }
        __threadfence();
    }
    __syncthreads();
}

// ---------------- persistent GRU recurrence ----------------
// 512 threads = 8 k-groups (46 k) x 64 b-lanes; each thread: 2 batches (lane, lane+64),
// 9 col-pair rows (6 cols x 3 gates, columns packed in f32x2).
#define RED(r, c, kg, lane) red[((((r) * 2 + (c)) * 4 + (kg)) << 6) + (lane)]

__global__ __launch_bounds__(THR_REC, 1) void gru_persistent(const float* __restrict__ Wh,
                                                             const float* __restrict__ bhb) {
    __shared__ float wsp[9 * H * 2];                   // 26.5 KB paired weights
    __shared__ unsigned long long red[9 * 2 * 4 * 64]; // 36.9 KB partials
    const int tid = threadIdx.x;
    const int bh = blockIdx.x & 1;
    const int cb = blockIdx.x >> 1;          // 0..61
    const int j0 = cb * 6;
    const int kg   = tid >> 6;               // 0..7
    const int lane = tid & 63;
    const int k0 = kg * 46;
    const int bA = bh * 128 + lane;          // batch 0
    const int bB = bA + 64;                  // batch 1

    // gate-role mapping (threads 0..383): p = pair, b2 = batch-local
    const int gp  = tid >> 7;
    const int gb2 = tid & 127;
    const int gc   = gb2 >> 6;               // which batch sub (0/1)
    const int glan = gb2 & 63;
    const int gbb = bh * 128 + gb2;
    const int gja = j0 + 2 * gp;
    const bool gate = (tid < 384) && (gja < H);

    // Load paired weights once: wsp[(row*H + k)*2 + {0,1}] = Wh[(g, j0+2p / +1)][k]
    for (int q = tid; q < 9 * H; q += THR_REC) {
        int row = q / H;
        int k   = q % H;
        int p = row / 3, g = row % 3;
        int ja = j0 + 2 * p, jb = ja + 1;
        float lo = (ja < H) ? Wh[((size_t)g * H + ja) * H + k] : 0.f;
        float hi = (jb < H) ? Wh[((size_t)g * H + jb) * H + k] : 0.f;
        wsp[(size_t)q * 2 + 0] = lo;
        wsp[(size_t)q * 2 + 1] = hi;
    }
    float gbias[2][3];
    if (gate) {
#pragma unroll
        for (int c = 0; c < 2; c++)
#pragma unroll
            for (int g = 0; g < 3; g++)
                gbias[c][g] = bhb[g * H + gja + c];
    }
    __syncthreads();

    for (int t = 0; t < T; t++) {
        const float* hprevT = g_temporalT + (size_t)(t - 1) * H * B;

        // ---- prefetch gi + hp (independent of matvec) ----
        float gi[2][3];
        float hp[2];
        if (gate) {
            const float* xp = g_xprojT + (size_t)t * G3 * B;
#pragma unroll
            for (int c = 0; c < 2; c++) {
                int j = gja + c;
                gi[c][0] = xp[((size_t)(0 * H + j)) * B + gbb];
                gi[c][1] = xp[((size_t)(1 * H + j)) * B + gbb];
                gi[c][2] = xp[((size_t)(2 * H + j)) * B + gbb];
                hp[c] = (t > 0) ? hprevT[(size_t)j * B + gbb] : 0.f;
            }
        }

        // ---- matvec: 46 k (23 x 2), 9 rows, 2 batches ----
        unsigned long long acc[9][2];
#pragma unroll
        for (int r = 0; r < 9; r++) { acc[r][0] = 0ull; acc[r][1] = 0ull; }

        if (t > 0) {
            const float* hkA = hprevT + (size_t)k0 * B + bA;
            const float* hkB = hprevT + (size_t)k0 * B + bB;
#pragma unroll 2
            for (int k2 = 0; k2 < 23; k2++) {
                int k = k0 + 2 * k2;
                unsigned long long ha0 = packdup(hkA[(size_t)(2 * k2 + 0) * B]);
                unsigned long long ha1 = packdup(hkA[(size_t)(2 * k2 + 1) * B]);
                unsigned long long hb0 = packdup(hkB[(size_t)(2 * k2 + 0) * B]);
                unsigned long long hb1 = packdup(hkB[(size_t)(2 * k2 + 1) * B]);
#pragma unroll
                for (int r = 0; r < 9; r++) {
                    ulonglong2 w = *(const ulonglong2*)&wsp[((size_t)r * H + k) * 2];
                    acc[r][0] = fma2(ha0, w.x, acc[r][0]);
                    acc[r][0] = fma2(ha1, w.y, acc[r][0]);
                    acc[r][1] = fma2(hb0, w.x, acc[r][1]);
                    acc[r][1] = fma2(hb1, w.y, acc[r][1]);
                }
            }
        }

        // ---- two-round reduction over 8 k-groups ----
        if (kg >= 4) {
#pragma unroll
            for (int r = 0; r < 9; r++) {
                RED(r, 0, kg - 4, lane) = acc[r][0];
                RED(r, 1, kg - 4, lane) = acc[r][1];
            }
        }
        __syncthreads();
        if (kg < 4) {
#pragma unroll
            for (int r = 0; r < 9; r++) {
                RED(r, 0, kg, lane) = add2(RED(r, 0, kg, lane), acc[r][0]);
                RED(r, 1, kg, lane) = add2(RED(r, 1, kg, lane), acc[r][1]);
            }
        }
        __syncthreads();

        // ---- gates ----
        if (gate) {
            unsigned long long s[3];
#pragma unroll
            for (int g = 0; g < 3; g++) {
                int r = gp * 3 + g;
                unsigned long long v = RED(r, gc, 0, glan);
                v = add2(v, RED(r, gc, 1, glan));
                v = add2(v, RED(r, gc, 2, glan));
                v = add2(v, RED(r, gc, 3, glan));
                s[g] = v;
            }
            float* houtT = g_temporalT + (size_t)t * H * B;
#pragma unroll
            for (int c = 0; c < 2; c++) {
                int j = gja + c;
                float gh_r = ((c == 0) ? lo32(s[0]) : hi32(s[0])) + gbias[c][0];
                float gh_z = ((c == 0) ? lo32(s[1]) : hi32(s[1])) + gbias[c][1];
                float gh_n = ((c == 0) ? lo32(s[2]) : hi32(s[2])) + gbias[c][2];
                float r = fsigmoid(gi[c][0] + gh_r);
                float z = fsigmoid(gi[c][1] + gh_z);
                float n = ftanh(gi[c][2] + r * gh_n);
                houtT[(size_t)j * B + gbb] = (1.f - z) * n + z * hp[c];
            }
        }

        if (t < T - 1) half_barrier(bh, cb, (unsigned)(t + 1));
    }
}

// ---------------- Kernel 3a: heads GEMM -> logits ----------------
__global__ __launch_bounds__(256) void heads_gemm(const float* __restrict__ Wc,
                                                  const float* __restrict__ bc,
                                                  const float* __restrict__ Wf,
                                                  const float* __restrict__ bf) {
    __shared__ float As[BK][128];
    __shared__ float Ws[BK][32];
    const int t  = blockIdx.x >> 1;
    const int b0 = (blockIdx.x & 1) * 128;
    const int tid = threadIdx.x;
    const int tx = tid % 8;
    const int ty = tid / 8;

    float acc[4][4];
#pragma unroll
    for (int i = 0; i < 4; i++)
#pragma unroll
        for (int j = 0; j < 4; j++) acc[i][j] = 0.f;

    const float* hT = g_temporalT + (size_t)t * H * B;

    for (int kt = 0; kt < H; kt += BK) {
#pragma unroll
        for (int l = 0; l < 2; l++) {
            int idx = tid + l * 256;
            int krow = idx >> 5;
            int bq = idx & 31;
            *(float4*)&As[krow][bq * 4] =
                *(const float4*)(hT + (size_t)(kt + krow) * B + b0 + bq * 4);
        }
        if (tid < 128) {
            int n = tid >> 2;
            int kq = tid & 3;
            float4 v = make_float4(0.f, 0.f, 0.f, 0.f);
            if (n < 2)       v = *(const float4*)(Wc + (size_t)n * H + kt + kq * 4);
            else if (n < 31) v = *(const float4*)(Wf + (size_t)(n - 2) * H + kt + kq * 4);
            Ws[kq * 4 + 0][n] = v.x;
            Ws[kq * 4 + 1][n] = v.y;
            Ws[kq * 4 + 2][n] = v.z;
            Ws[kq * 4 + 3][n] = v.w;
        }
        __syncthreads();
#pragma unroll
        for (int k = 0; k < BK; k++) {
            float a[4], w[4];
            *(float4*)a = *(const float4*)&As[k][ty * 4];
            *(float4*)w = *(const float4*)&Ws[k][tx * 4];
#pragma unroll
            for (int i = 0; i < 4; i++)
#pragma unroll
                for (int j = 0; j < 4; j++)
                    acc[i][j] = fmaf(a[i], w[j], acc[i][j]);
        }
        __syncthreads();
    }

#pragma unroll
    for (int i = 0; i < 4; i++) {
        int b = b0 + ty * 4 + i;
        float4 v;
        float* vp = (float*)&v;
#pragma unroll
        for (int j = 0; j < 4; j++) {
            int n = tx * 4 + j;
            float bias = (n < 2) ? bc[n] : ((n < 31) ? bf[n - 2] : 0.f);
            vp[j] = acc[i][j] + bias;
        }
        *(float4*)&g_logits[((size_t)t * B + b) * 32 + tx * 4] = v;
    }
}

// ---------------- Kernel 3b: activations ----------------
__global__ __launch_bounds__(256) void act_kernel(float* __restrict__ out) {
    int idx = blockIdx.x * blockDim.x + threadIdx.x;
    if (idx >= B * T) return;
    int t = idx >> 8;
    int b = idx & 255;
    const float* lg = g_logits + (size_t)idx * 32;
    float logit[32];
#pragma unroll
    for (int q = 0; q < 8; q++)
        *(float4*)&logit[q * 4] = *(const float4*)&lg[q * 4];

    float l0 = logit[0], l1 = logit[1];
    float m = fmaxf(l0, l1);
    float e0 = __expf(l0 - m), e1 = __expf(l1 - m);
    float inv = 1.f / (e0 + e1);
    size_t oidx = (size_t)b * T + t;
    g_scores[oidx * 2 + 0] = e0 * inv;
    g_scores[oidx * 2 + 1] = e1 * inv;

    float* fine = out + OUT_FINE_OFF + oidx * NC;
#pragma unroll
    for (int i = 0; i < NC; i++) fine[i] = fsigmoid(logit[2 + i]);
}

// ---------------- Kernel 4: NMS + decisions ----------------
__global__ void nms_kernel(float* __restrict__ out) {
    int idx = blockIdx.x * blockDim.x + threadIdx.x;
    if (idx >= B * T) return;
    int b = idx / T;
    int t = idx % T;
    const float* sb = g_scores + (size_t)b * T * 2;
    float s0 = sb[t * 2 + 0];
    float s1 = sb[t * 2 + 1];
    float wmin = INFINITY;
#pragma unroll
    for (int k = -2; k <= 2; k++) {
        int tt = t + k;
        if (tt >= 0 && tt < T) wmin = fminf(wmin, sb[tt * 2]);
    }
    bool keep = (s0 == wmin);
    float o0 = keep ? s0 : 0.f;
    float o1 = keep ? s1 : 0.f;
    out[idx] = (o1 > o0) ? 1.0f : 0.0f;
    out[OUT_NMS_OFF + (size_t)idx * 2 + 0] = o0;
    out[OUT_NMS_OFF + (size_t)idx * 2 + 1] = o1;
}

// ---------------- launch ----------------
extern "C" void kernel_launch(void* const* d_in, const int* in_sizes, int n_in,
                              void* d_out, int out_size) {
    const float* feat = (const float*)d_in[0];
    const float* Wi  = (const float*)d_in[2];
    const float* Wh  = (const float*)d_in[3];
    const float* bi  = (const float*)d_in[4];
    const float* bhb = (const float*)d_in[5];
    const float* Wc  = (const float*)d_in[6];
    const float* bc  = (const float*)d_in[7];
    const float* Wf  = (const float*)d_in[8];
    const float* bf  = (const float*)d_in[9];
    float* out = (float*)d_out;

    // launch order keeps gru_persistent in the ncu-profiled slot (4th launch)
    reset_arrive_kernel<<<1, 256>>>();                 // 1
    dim3 g1(T * 2, (G3 + 63) / 64);
    xproj_gemm<<<g1, 256>>>(feat, Wi, bi);             // 2
    reset_release_kernel<<<1, 64>>>();                 // 3
    gru_persistent<<<GRID_REC, THR_REC>>>(Wh, bhb);    // 4  <- profiled
    heads_gemm<<<T * 2, 256>>>(Wc, bc, Wf, bf);        // 5
    act_kernel<<<(B * T + 255) / 256, 256>>>(out);     // 6
    nms_kernel<<<(B * T + 255) / 256, 256>>>(out);     // 7
}